// round 4
// baseline (speedup 1.0000x reference)
#include <cuda_runtime.h>

#define B_ROWS   16384
#define NFEAT    1024
#define FACTORS  64
#define TOTAL    524288

// G table (256 KB) reused ~512x per row -> pin in L1 (evict_last).
// H rows have little per-SM reuse -> evict_first.
__device__ __forceinline__ float4 ldg_el4(const float* p) {
    float4 v;
    asm("ld.global.nc.L1::evict_last.v4.f32 {%0,%1,%2,%3}, [%4];"
        : "=f"(v.x), "=f"(v.y), "=f"(v.z), "=f"(v.w) : "l"(p));
    return v;
}
__device__ __forceinline__ float4 ldg_ef4(const float* p) {
    float4 v;
    asm("ld.global.nc.L1::evict_first.v4.f32 {%0,%1,%2,%3}, [%4];"
        : "=f"(v.x), "=f"(v.y), "=f"(v.z), "=f"(v.w) : "l"(p));
    return v;
}

__global__ void init_out_kernel(float* out) {
    if (threadIdx.x == 0) out[0] = 0.0f;
}

__global__ __launch_bounds__(256) void kgflex_halfwarp_kernel(
    const int*   __restrict__ user,
    const int*   __restrict__ sample_idx,
    const int*   __restrict__ feat_idx,
    const float* __restrict__ H,
    const float* __restrict__ G,
    const float* __restrict__ K,
    float*       __restrict__ out)
{
    const int lane = threadIdx.x & 31;
    const int half = lane >> 4;        // 0: even items, 1: odd items
    const int lh   = lane & 15;        // position within half-warp

    // 524288 threads = 16384 warps x 32 items: exact cover.
    const int t = blockIdx.x * blockDim.x + threadIdx.x;

    // --- per-lane preload of this warp's 32 items
    const int b  = __ldg(sample_idx + t);
    const int n  = __ldg(feat_idx + t);
    const int u  = __ldg(user + b);
    const int un = (u << 10) | n;            // u*1024 + n (27 bits)
    const float kv_lane = __ldg(K + un);     // K[u][n], gathered up front

    // lane covers factors [4*lh, 4*lh+4) of its half's item
    const float* Hb = H + 4 * lh;
    const float* Gb = G + 4 * lh;

    float acc = 0.0f;

    // --- prefetch pair 0
    int   unj = __shfl_sync(0xFFFFFFFFu, un, half);
    float kvj = __shfl_sync(0xFFFFFFFFu, kv_lane, half);
    float4 h = ldg_ef4(Hb + ((unj >> 4) & ~63));      // (un>>10)*64
    float4 g = ldg_el4(Gb + ((unj << 6) & 0xFFFF));   // (un&1023)*64

    // --- 15 pipelined iterations + tail (2 items per iteration)
    #pragma unroll
    for (int j = 0; j < 15; ++j) {
        const int   unn = __shfl_sync(0xFFFFFFFFu, un, 2 * (j + 1) + half);
        const float kvn = __shfl_sync(0xFFFFFFFFu, kv_lane, 2 * (j + 1) + half);
        const float4 hn = ldg_ef4(Hb + ((unn >> 4) & ~63));
        const float4 gn = ldg_el4(Gb + ((unn << 6) & 0xFFFF));

        float d = h.x * g.x;
        d = fmaf(h.y, g.y, d);
        d = fmaf(h.z, g.z, d);
        d = fmaf(h.w, g.w, d);
        acc = fmaf(kvj, d, acc);

        h = hn; g = gn; kvj = kvn;
    }
    {   // tail: consume last pair
        float d = h.x * g.x;
        d = fmaf(h.y, g.y, d);
        d = fmaf(h.z, g.z, d);
        d = fmaf(h.w, g.w, d);
        acc = fmaf(kvj, d, acc);
    }

    // --- single reduction (both halves sum into the same total)
    #pragma unroll
    for (int off = 16; off > 0; off >>= 1)
        acc += __shfl_xor_sync(0xFFFFFFFFu, acc, off);

    __shared__ float warp_sums[8];
    const int wid = threadIdx.x >> 5;
    if (lane == 0) warp_sums[wid] = acc;
    __syncthreads();
    if (wid == 0) {
        float v = (lane < 8) ? warp_sums[lane] : 0.0f;
        #pragma unroll
        for (int off = 4; off > 0; off >>= 1)
            v += __shfl_xor_sync(0xFFFFFFFFu, v, off);
        if (lane == 0) atomicAdd(out, v);
    }
}

extern "C" void kernel_launch(void* const* d_in, const int* in_sizes, int n_in,
                              void* d_out, int out_size)
{
    const int*   user       = (const int*)  d_in[0];
    const int*   sample_idx = (const int*)  d_in[1];
    const int*   feat_idx   = (const int*)  d_in[2];
    const float* H          = (const float*)d_in[3];
    const float* G          = (const float*)d_in[4];
    const float* K          = (const float*)d_in[5];
    float*       out        = (float*)d_out;

    (void)in_sizes; (void)n_in; (void)out_size;

    init_out_kernel<<<1, 32>>>(out);

    const int threads = 256;
    const int blocks  = TOTAL / threads;   // 2048, exact
    kgflex_halfwarp_kernel<<<blocks, threads>>>(user, sample_idx, feat_idx,
                                                H, G, K, out);
}